// round 13
// baseline (speedup 1.0000x reference)
#include <cuda_runtime.h>
#include <cuda_bf16.h>

// Problem constants (fixed by setup_inputs): B=2, C=16, H=W=256, Cctx=64, Cqk=2, Cv=1
#define BB   2
#define CC   16
#define HH   256
#define WW   256
#define CTX  64
#define HW   (HH * WW)          // 65536
#define HW4  (HW / 4)           // 16384
#define W4   (WW / 4)           // 64
#define LOG2E 1.4426950408889634f

// Scratch (all L2-resident). Each array written by exactly one kernel.
__device__ float2 g_K01[BB * HW];
__device__ float  g_V  [BB * HW];
__device__ float2 g_Q01[BB * HW];

// ---------------------------------------------------------------------------
// Kernel 1a: y -> v projection (the 32MB stream). WARP-level channel split:
// warp s (0..7) of each block handles channels [8s, 8s+8) for the SAME 32
// float4 position-groups -> every LDG.128 is 32 consecutive float4s = 512B
// fully coalesced. 8 independent loads + 4 accum regs per thread => all loads
// in flight at ~56 warps/SM. Cross-warp reduce via shared; warp 0 writes.
// ---------------------------------------------------------------------------
__global__ void __launch_bounds__(256) projy_kernel(
    const float* __restrict__ y,
    const float* __restrict__ Wv, const float* __restrict__ bv)
{
    __shared__ float4 sP[8][32];

    const int warp  = threadIdx.x >> 5;           // channel split 0..7
    const int lane  = threadIdx.x & 31;
    const int g     = blockIdx.x * 32 + lane;     // float4 pos-group [0, 32768)
    const int b     = g >> 14;                    // whole block same b (32 | 16384)
    const int p4    = g & (HW4 - 1);

    float4 v = make_float4(0.f, 0.f, 0.f, 0.f);
    const float4* yb = (const float4*)y + (size_t)b * CTX * HW4 + p4;
#pragma unroll
    for (int i = 0; i < 8; i++) {
        int c = warp * 8 + i;
        float4 yv = __ldg(yb + c * HW4);
        float wv  = __ldg(Wv + c);
        v.x = fmaf(wv, yv.x, v.x); v.y = fmaf(wv, yv.y, v.y);
        v.z = fmaf(wv, yv.z, v.z); v.w = fmaf(wv, yv.w, v.w);
    }

    sP[warp][lane] = v;
    __syncthreads();

    if (warp == 0) {
        float4 acc = sP[0][lane];
#pragma unroll
        for (int j = 1; j < 8; j++) {
            float4 t = sP[j][lane];
            acc.x += t.x; acc.y += t.y; acc.z += t.z; acc.w += t.w;
        }
        float bv0 = __ldg(bv);
        ((float4*)g_V)[g] = make_float4(acc.x + bv0, acc.y + bv0,
                                        acc.z + bv0, acc.w + bv0);
    }
}

// ---------------------------------------------------------------------------
// Kernel 1b: x -> q, k projection (8MB stream). 4 threads (s = tid&3) share
// one float4 position-group; butterfly-reduce (xor 1,2); lane s==0 adds
// biases, scales q by log2(e). (Verbatim from the passing R11/R12 kernel.)
// ---------------------------------------------------------------------------
__global__ void __launch_bounds__(256) projx_kernel(
    const float* __restrict__ x,
    const float* __restrict__ Wq, const float* __restrict__ bq,
    const float* __restrict__ Wk, const float* __restrict__ bk)
{
    const int tid = blockIdx.x * 256 + threadIdx.x;   // [0, 131072)
    const int g   = tid >> 2;                         // float4 pos-group [0, 32768)
    const int s   = tid & 3;
    const int b   = g >> 14;
    const int p4  = g & (HW4 - 1);

    float4 k0 = make_float4(0.f,0.f,0.f,0.f);
    float4 k1 = make_float4(0.f,0.f,0.f,0.f);
    float4 q0 = make_float4(0.f,0.f,0.f,0.f);
    float4 q1 = make_float4(0.f,0.f,0.f,0.f);

    const float4* xb = (const float4*)x + (size_t)b * CC * HW4 + p4;
#pragma unroll
    for (int i = 0; i < 4; i++) {
        int c = s * 4 + i;
        float4 xv = __ldg(xb + c * HW4);
        float wk0 = __ldg(Wk + c), wk1 = __ldg(Wk + CC + c);
        float wq0 = __ldg(Wq + c), wq1 = __ldg(Wq + CC + c);
        k0.x = fmaf(wk0, xv.x, k0.x); k0.y = fmaf(wk0, xv.y, k0.y);
        k0.z = fmaf(wk0, xv.z, k0.z); k0.w = fmaf(wk0, xv.w, k0.w);
        k1.x = fmaf(wk1, xv.x, k1.x); k1.y = fmaf(wk1, xv.y, k1.y);
        k1.z = fmaf(wk1, xv.z, k1.z); k1.w = fmaf(wk1, xv.w, k1.w);
        q0.x = fmaf(wq0, xv.x, q0.x); q0.y = fmaf(wq0, xv.y, q0.y);
        q0.z = fmaf(wq0, xv.z, q0.z); q0.w = fmaf(wq0, xv.w, q0.w);
        q1.x = fmaf(wq1, xv.x, q1.x); q1.y = fmaf(wq1, xv.y, q1.y);
        q1.z = fmaf(wq1, xv.z, q1.z); q1.w = fmaf(wq1, xv.w, q1.w);
    }

#define RED4(f) \
    f += __shfl_xor_sync(0xffffffffu, f, 1); \
    f += __shfl_xor_sync(0xffffffffu, f, 2);
    RED4(k0.x) RED4(k0.y) RED4(k0.z) RED4(k0.w)
    RED4(k1.x) RED4(k1.y) RED4(k1.z) RED4(k1.w)
    RED4(q0.x) RED4(q0.y) RED4(q0.z) RED4(q0.w)
    RED4(q1.x) RED4(q1.y) RED4(q1.z) RED4(q1.w)
#undef RED4

    if (s == 0) {
        float bk0 = __ldg(bk + 0), bk1 = __ldg(bk + 1);
        float bq0 = __ldg(bq + 0), bq1 = __ldg(bq + 1);

        float4* K01o = (float4*)g_K01 + (size_t)g * 2;
        K01o[0] = make_float4(k0.x + bk0, k1.x + bk1, k0.y + bk0, k1.y + bk1);
        K01o[1] = make_float4(k0.z + bk0, k1.z + bk1, k0.w + bk0, k1.w + bk1);

        float4* Q01o = (float4*)g_Q01 + (size_t)g * 2;
        Q01o[0] = make_float4((q0.x + bq0) * LOG2E, (q1.x + bq1) * LOG2E,
                              (q0.y + bq0) * LOG2E, (q1.y + bq1) * LOG2E);
        Q01o[1] = make_float4((q0.z + bq0) * LOG2E, (q1.z + bq1) * LOG2E,
                              (q0.w + bq0) * LOG2E, (q1.w + bq1) * LOG2E);
    }
}

// ---------------------------------------------------------------------------
// Kernel 2: FUSED attention + softmax-normalize + gamma + residual.
// One CTA per (b, h); 512 threads split BY ATTENTION TYPE:
//   threads   0..255 (w = tid)      : column walk — g_K01/g_V at (g, w),
//                                     coalesced LDG, diagonal subtracted once.
//   threads 256..511 (w = tid-256)  : row walk — staged row k/v in shared,
//                                     pure LDS broadcast.
// The two halves pair-reduce (s, acc) via shared, column threads compute
// res = gamma*acc/s, and a float4 epilogue writes all 16 output channels
// with the x residual. No partial arrays, no combine kernel.
// ---------------------------------------------------------------------------
__global__ void __launch_bounds__(512, 3) attn_kernel(
    const float* __restrict__ x,
    const float* __restrict__ gamma,
    float* __restrict__ out)
{
    __shared__ float2 sK[256];     // row h: k at (h, g)
    __shared__ float  sV[256];     // row h: v at (h, g)
    __shared__ float2 sRed[256];   // row-half partial (s, acc)
    __shared__ float  sRes[256];   // final res per w

    const int tid  = threadIdx.x;
    const int half = tid >> 8;             // 0 = column walk, 1 = row walk
    const int w    = tid & 255;

    const int blk  = blockIdx.x;           // [0, BB*HH)
    const int b    = blk >> 8;
    const int h    = blk & 255;
    const int plane = b * HW;
    const int rowbase = plane + h * WW;

    // Stage row k/v (256 entries) into shared.
    if (half == 0) sK[w] = g_K01[rowbase + w];
    else           sV[w] = g_V [rowbase + w];

    const float2 q = g_Q01[rowbase + w];
    __syncthreads();

    float s   = 0.0f;
    float acc = 0.0f;

    if (half == 0) {
        // Column attention: walk g, coalesced global loads.
        const float2* Kc = g_K01 + plane + w;
        const float*  Vc = g_V   + plane + w;
#pragma unroll 8
        for (int g = 0; g < HH; g++) {
            float2 kc = Kc[g * WW];
            float  vc = Vc[g * WW];
            float  e  = fmaf(q.x, kc.x, q.y * kc.y);
            float  pe;
            asm("ex2.approx.f32 %0, %1;" : "=f"(pe) : "f"(e));
            s   += pe;
            acc  = fmaf(pe, vc, acc);
        }
        // Subtract the masked diagonal term (g == h).
        {
            float2 kd = g_K01[rowbase + w];
            float  vd = g_V [rowbase + w];
            float  ed = fmaf(q.x, kd.x, q.y * kd.y);
            float  pd;
            asm("ex2.approx.f32 %0, %1;" : "=f"(pd) : "f"(ed));
            s   -= pd;
            acc  = fmaf(-pd, vd, acc);
        }
    } else {
        // Row attention: walk g, broadcast shared loads (no mask).
#pragma unroll 8
        for (int g = 0; g < HH; g++) {
            float2 kr = sK[g];
            float  vr = sV[g];
            float  e2 = fmaf(q.x, kr.x, q.y * kr.y);
            float  pe2;
            asm("ex2.approx.f32 %0, %1;" : "=f"(pe2) : "f"(e2));
            s   += pe2;
            acc  = fmaf(pe2, vr, acc);
        }
        sRed[w] = make_float2(s, acc);
    }
    __syncthreads();

    if (half == 0) {
        float2 rr = sRed[w];
        float  st = s + rr.x;
        float  at = acc + rr.y;
        sRes[w] = __ldg(gamma) * at / st;
    }
    __syncthreads();

    // Epilogue: 16 channels x 64 float4-groups = 1024 float4 stores per CTA;
    // each thread does 2 (channel c = tid>>5, w-groups wg and wg+32).
    {
        const int c  = tid >> 5;           // 0..15
        const int wg = tid & 31;
        const float4* resv = (const float4*)sRes;
        const float4* xb = (const float4*)x + (size_t)(b * CC + c) * HW4 + h * W4;
        float4*       ob = (float4*)out     + (size_t)(b * CC + c) * HW4 + h * W4;
#pragma unroll
        for (int t = 0; t < 2; t++) {
            int w4 = wg + t * 32;          // 0..63
            float4 r4 = resv[w4];
            float4 xv = __ldg(xb + w4);
            ob[w4] = make_float4(r4.x + xv.x, r4.y + xv.y,
                                 r4.z + xv.z, r4.w + xv.w);
        }
    }
}

// ---------------------------------------------------------------------------
// kernel_launch: inputs per metadata order:
//   0:x (B,C,H,W) 1:y (B,64,H,W) 2:Wq (2,16) 3:bq (2) 4:Wk (2,16) 5:bk (2)
//   6:Wv (1,64)  7:bv (1)        8:gamma (1)
// ---------------------------------------------------------------------------
extern "C" void kernel_launch(void* const* d_in, const int* in_sizes, int n_in,
                              void* d_out, int out_size)
{
    const float* x     = (const float*)d_in[0];
    const float* y     = (const float*)d_in[1];
    const float* Wq    = (const float*)d_in[2];
    const float* bq    = (const float*)d_in[3];
    const float* Wk    = (const float*)d_in[4];
    const float* bk    = (const float*)d_in[5];
    const float* Wv    = (const float*)d_in[6];
    const float* bv    = (const float*)d_in[7];
    const float* gamma = (const float*)d_in[8];
    float* out = (float*)d_out;

    projy_kernel<<<1024, 256>>>(y, Wv, bv);
    projx_kernel<<<512, 256>>>(x, Wq, bq, Wk, bk);
    attn_kernel<<<BB * HH, 512>>>(x, gamma, out);
}

// round 14
// speedup vs baseline: 1.1980x; 1.1980x over previous
#include <cuda_runtime.h>
#include <cuda_bf16.h>

// Problem constants (fixed by setup_inputs): B=2, C=16, H=W=256, Cctx=64, Cqk=2, Cv=1
#define BB   2
#define CC   16
#define HH   256
#define WW   256
#define CTX  64
#define HW   (HH * WW)          // 65536
#define HW4  (HW / 4)           // 16384
#define W4   (WW / 4)           // 64
#define LOG2E 1.4426950408889634f

// Scratch (all L2-resident). Each array written by exactly one kernel.
__device__ float2 g_K01[BB * HW];
__device__ float  g_V  [BB * HW];
__device__ float2 g_Q01[BB * HW];

// ---------------------------------------------------------------------------
// Kernel 1a: y -> v projection (32MB stream). Warp-level channel split
// (measured 9.2us @ 3.6TB/s, occ 77%): warp s handles channels [8s,8s+8) for
// the same 32 float4 pos-groups; every LDG.128 is 512B fully coalesced.
// (Verbatim from R13 — measured good.)
// ---------------------------------------------------------------------------
__global__ void __launch_bounds__(256) projy_kernel(
    const float* __restrict__ y,
    const float* __restrict__ Wv, const float* __restrict__ bv)
{
    __shared__ float4 sP[8][32];

    const int warp  = threadIdx.x >> 5;           // channel split 0..7
    const int lane  = threadIdx.x & 31;
    const int g     = blockIdx.x * 32 + lane;     // float4 pos-group [0, 32768)
    const int b     = g >> 14;
    const int p4    = g & (HW4 - 1);

    float4 v = make_float4(0.f, 0.f, 0.f, 0.f);
    const float4* yb = (const float4*)y + (size_t)b * CTX * HW4 + p4;
#pragma unroll
    for (int i = 0; i < 8; i++) {
        int c = warp * 8 + i;
        float4 yv = __ldg(yb + c * HW4);
        float wv  = __ldg(Wv + c);
        v.x = fmaf(wv, yv.x, v.x); v.y = fmaf(wv, yv.y, v.y);
        v.z = fmaf(wv, yv.z, v.z); v.w = fmaf(wv, yv.w, v.w);
    }

    sP[warp][lane] = v;
    __syncthreads();

    if (warp == 0) {
        float4 acc = sP[0][lane];
#pragma unroll
        for (int j = 1; j < 8; j++) {
            float4 t = sP[j][lane];
            acc.x += t.x; acc.y += t.y; acc.z += t.z; acc.w += t.w;
        }
        float bv0 = __ldg(bv);
        ((float4*)g_V)[g] = make_float4(acc.x + bv0, acc.y + bv0,
                                        acc.z + bv0, acc.w + bv0);
    }
}

// ---------------------------------------------------------------------------
// Kernel 1b: x -> q, k projection (8MB stream). 4-thread split + butterfly
// reduce. (Verbatim from the passing R11/R12/R13 kernel.)
// ---------------------------------------------------------------------------
__global__ void __launch_bounds__(256) projx_kernel(
    const float* __restrict__ x,
    const float* __restrict__ Wq, const float* __restrict__ bq,
    const float* __restrict__ Wk, const float* __restrict__ bk)
{
    const int tid = blockIdx.x * 256 + threadIdx.x;   // [0, 131072)
    const int g   = tid >> 2;                         // float4 pos-group [0, 32768)
    const int s   = tid & 3;
    const int b   = g >> 14;
    const int p4  = g & (HW4 - 1);

    float4 k0 = make_float4(0.f,0.f,0.f,0.f);
    float4 k1 = make_float4(0.f,0.f,0.f,0.f);
    float4 q0 = make_float4(0.f,0.f,0.f,0.f);
    float4 q1 = make_float4(0.f,0.f,0.f,0.f);

    const float4* xb = (const float4*)x + (size_t)b * CC * HW4 + p4;
#pragma unroll
    for (int i = 0; i < 4; i++) {
        int c = s * 4 + i;
        float4 xv = __ldg(xb + c * HW4);
        float wk0 = __ldg(Wk + c), wk1 = __ldg(Wk + CC + c);
        float wq0 = __ldg(Wq + c), wq1 = __ldg(Wq + CC + c);
        k0.x = fmaf(wk0, xv.x, k0.x); k0.y = fmaf(wk0, xv.y, k0.y);
        k0.z = fmaf(wk0, xv.z, k0.z); k0.w = fmaf(wk0, xv.w, k0.w);
        k1.x = fmaf(wk1, xv.x, k1.x); k1.y = fmaf(wk1, xv.y, k1.y);
        k1.z = fmaf(wk1, xv.z, k1.z); k1.w = fmaf(wk1, xv.w, k1.w);
        q0.x = fmaf(wq0, xv.x, q0.x); q0.y = fmaf(wq0, xv.y, q0.y);
        q0.z = fmaf(wq0, xv.z, q0.z); q0.w = fmaf(wq0, xv.w, q0.w);
        q1.x = fmaf(wq1, xv.x, q1.x); q1.y = fmaf(wq1, xv.y, q1.y);
        q1.w = fmaf(wq1, xv.w, q1.w); q1.z = fmaf(wq1, xv.z, q1.z);
    }

#define RED4(f) \
    f += __shfl_xor_sync(0xffffffffu, f, 1); \
    f += __shfl_xor_sync(0xffffffffu, f, 2);
    RED4(k0.x) RED4(k0.y) RED4(k0.z) RED4(k0.w)
    RED4(k1.x) RED4(k1.y) RED4(k1.z) RED4(k1.w)
    RED4(q0.x) RED4(q0.y) RED4(q0.z) RED4(q0.w)
    RED4(q1.x) RED4(q1.y) RED4(q1.z) RED4(q1.w)
#undef RED4

    if (s == 0) {
        float bk0 = __ldg(bk + 0), bk1 = __ldg(bk + 1);
        float bq0 = __ldg(bq + 0), bq1 = __ldg(bq + 1);

        float4* K01o = (float4*)g_K01 + (size_t)g * 2;
        K01o[0] = make_float4(k0.x + bk0, k1.x + bk1, k0.y + bk0, k1.y + bk1);
        K01o[1] = make_float4(k0.z + bk0, k1.z + bk1, k0.w + bk0, k1.w + bk1);

        float4* Q01o = (float4*)g_Q01 + (size_t)g * 2;
        Q01o[0] = make_float4((q0.x + bq0) * LOG2E, (q1.x + bq1) * LOG2E,
                              (q0.y + bq0) * LOG2E, (q1.y + bq1) * LOG2E);
        Q01o[1] = make_float4((q0.z + bq0) * LOG2E, (q1.z + bq1) * LOG2E,
                              (q0.w + bq0) * LOG2E, (q1.w + bq1) * LOG2E);
    }
}

// ---------------------------------------------------------------------------
// Kernel 2: attention with the R12-PROVEN inner loop + fused epilogue.
// One CTA per (b, h); 512 threads = 2 g-splits x 256 w. Each thread runs the
// R12-measured interleaved loop: 128 column-g (coalesced LDG) + 128 row-g
// (LDS broadcast) per iteration paired — balanced LDG/LDS/MUFU pipe mix.
// Then the two splits pair-reduce (s, acc) through shared and the CTA writes
// all 16 output channels + residual (float4). No g_part, no combine kernel.
// ---------------------------------------------------------------------------
__global__ void __launch_bounds__(512, 4) attn_kernel(
    const float* __restrict__ x,
    const float* __restrict__ gamma,
    float* __restrict__ out)
{
    __shared__ float2 sK[256];     // row h: k at (h, g), all 256 g
    __shared__ float  sV[256];     // row h: v at (h, g)
    __shared__ float2 sRed[256];   // split-1 partial (s, acc)
    __shared__ float  sRes[256];   // final res per w

    const int tid   = threadIdx.x;
    const int split = tid >> 8;            // g-range: [0,128) or [128,256)
    const int w     = tid & 255;
    const int g0    = split << 7;

    const int blk   = blockIdx.x;          // [0, BB*HH)
    const int b     = blk >> 8;
    const int h     = blk & 255;
    const int plane   = b * HW;
    const int rowbase = plane + h * WW;

    // Stage full row k/v (256 entries) into shared: split 0 loads K, 1 loads V.
    if (split == 0) sK[w] = g_K01[rowbase + w];
    else            sV[w] = g_V [rowbase + w];

    const float2 q = g_Q01[rowbase + w];
    __syncthreads();

    const float2* Kc = g_K01 + plane + g0 * WW + w;   // column walk, coalesced
    const float*  Vc = g_V   + plane + g0 * WW + w;

    float s   = 0.0f;
    float acc = 0.0f;

#pragma unroll 4
    for (int j = 0; j < 128; j++) {
        // --- column attention (eH), diagonal included (removed below) ---
        float2 kc = Kc[j * WW];
        float  vc = Vc[j * WW];
        float  e  = fmaf(q.x, kc.x, q.y * kc.y);
        float  pe;
        asm("ex2.approx.f32 %0, %1;" : "=f"(pe) : "f"(e));
        s   += pe;
        acc  = fmaf(pe, vc, acc);

        // --- row attention (eW), no mask ---
        float2 kr = sK[g0 + j];
        float  vr = sV[g0 + j];
        float  e2 = fmaf(q.x, kr.x, q.y * kr.y);
        float  pe2;
        asm("ex2.approx.f32 %0, %1;" : "=f"(pe2) : "f"(e2));
        s   += pe2;
        acc  = fmaf(pe2, vr, acc);
    }

    // Subtract the masked diagonal term (g == h) if it fell in this split.
    if ((unsigned)(h - g0) < 128u) {
        float2 kd = g_K01[rowbase + w];
        float  vd = g_V [rowbase + w];
        float  ed = fmaf(q.x, kd.x, q.y * kd.y);
        float  pd;
        asm("ex2.approx.f32 %0, %1;" : "=f"(pd) : "f"(ed));
        s   -= pd;
        acc  = fmaf(-pd, vd, acc);
    }

    // Pair-reduce the two splits through shared.
    if (split == 1) sRed[w] = make_float2(s, acc);
    __syncthreads();
    if (split == 0) {
        float2 rr = sRed[w];
        sRes[w] = __ldg(gamma) * (acc + rr.y) / (s + rr.x);
    }
    __syncthreads();

    // Epilogue: 16 channels x 64 float4-groups = 1024 float4 stores per CTA;
    // each thread does 2 (channel c = tid>>5, w-groups wg and wg+32).
    // (Index pattern verified correct in R13.)
    {
        const int c  = tid >> 5;           // 0..15
        const int wg = tid & 31;
        const float4* resv = (const float4*)sRes;
        const float4* xb = (const float4*)x + (size_t)(b * CC + c) * HW4 + h * W4;
        float4*       ob = (float4*)out     + (size_t)(b * CC + c) * HW4 + h * W4;
#pragma unroll
        for (int t = 0; t < 2; t++) {
            int w4 = wg + t * 32;          // 0..63
            float4 r4 = resv[w4];
            float4 xv = __ldg(xb + w4);
            ob[w4] = make_float4(r4.x + xv.x, r4.y + xv.y,
                                 r4.z + xv.z, r4.w + xv.w);
        }
    }
}

// ---------------------------------------------------------------------------
// kernel_launch: inputs per metadata order:
//   0:x (B,C,H,W) 1:y (B,64,H,W) 2:Wq (2,16) 3:bq (2) 4:Wk (2,16) 5:bk (2)
//   6:Wv (1,64)  7:bv (1)        8:gamma (1)
// ---------------------------------------------------------------------------
extern "C" void kernel_launch(void* const* d_in, const int* in_sizes, int n_in,
                              void* d_out, int out_size)
{
    const float* x     = (const float*)d_in[0];
    const float* y     = (const float*)d_in[1];
    const float* Wq    = (const float*)d_in[2];
    const float* bq    = (const float*)d_in[3];
    const float* Wk    = (const float*)d_in[4];
    const float* bk    = (const float*)d_in[5];
    const float* Wv    = (const float*)d_in[6];
    const float* bv    = (const float*)d_in[7];
    const float* gamma = (const float*)d_in[8];
    float* out = (float*)d_out;

    projy_kernel<<<1024, 256>>>(y, Wv, bv);
    projx_kernel<<<512, 256>>>(x, Wq, bq, Wk, bk);
    attn_kernel<<<BB * HH, 512>>>(x, gamma, out);
}

// round 15
// speedup vs baseline: 1.2516x; 1.0447x over previous
#include <cuda_runtime.h>
#include <cuda_bf16.h>

// Problem constants (fixed by setup_inputs): B=2, C=16, H=W=256, Cctx=64, Cqk=2, Cv=1
#define BB   2
#define CC   16
#define HH   256
#define WW   256
#define CTX  64
#define HW   (HH * WW)          // 65536
#define HW4  (HW / 4)           // 16384
#define LOG2E 1.4426950408889634f

// Scratch (all L2-resident). Each array written by exactly one kernel.
__device__ float2 g_K01[BB * HW];
__device__ float  g_V  [BB * HW];
__device__ float2 g_Q01[BB * HW];
__device__ float  g_res[BB * HW];   // normalized gamma*acc/s per position

// ---------------------------------------------------------------------------
// Kernel 1a: y -> v projection (32MB stream). Warp-level channel split:
// warp s handles channels [8s,8s+8) for the same 32 float4 pos-groups; every
// LDG.128 is 512B fully coalesced. R14 fix: all 8 loads are materialized into
// named float4 regs BEFORE any FMA and no occupancy-min clause caps regs, so
// ptxas front-batches all 8 (32 dest regs) -> ~2x bytes in flight vs the
// measured regs=32 version (45% DRAM).
// ---------------------------------------------------------------------------
__global__ void __launch_bounds__(256) projy_kernel(
    const float* __restrict__ y,
    const float* __restrict__ Wv, const float* __restrict__ bv)
{
    __shared__ float4 sP[8][32];

    const int warp  = threadIdx.x >> 5;           // channel split 0..7
    const int lane  = threadIdx.x & 31;
    const int g     = blockIdx.x * 32 + lane;     // float4 pos-group [0, 32768)
    const int b     = g >> 14;
    const int p4    = g & (HW4 - 1);

    const float4* yb = (const float4*)y + (size_t)b * CTX * HW4
                                        + (size_t)(warp * 8) * HW4 + p4;
    // Batch ALL loads first (independent, 32 dest regs).
    float4 y0 = __ldg(yb + 0 * HW4);
    float4 y1 = __ldg(yb + 1 * HW4);
    float4 y2 = __ldg(yb + 2 * HW4);
    float4 y3 = __ldg(yb + 3 * HW4);
    float4 y4 = __ldg(yb + 4 * HW4);
    float4 y5 = __ldg(yb + 5 * HW4);
    float4 y6 = __ldg(yb + 6 * HW4);
    float4 y7 = __ldg(yb + 7 * HW4);
    float w0 = __ldg(Wv + warp * 8 + 0);
    float w1 = __ldg(Wv + warp * 8 + 1);
    float w2 = __ldg(Wv + warp * 8 + 2);
    float w3 = __ldg(Wv + warp * 8 + 3);
    float w4 = __ldg(Wv + warp * 8 + 4);
    float w5 = __ldg(Wv + warp * 8 + 5);
    float w6 = __ldg(Wv + warp * 8 + 6);
    float w7 = __ldg(Wv + warp * 8 + 7);

    float4 v;
    v.x = fmaf(w0, y0.x, fmaf(w1, y1.x, fmaf(w2, y2.x, fmaf(w3, y3.x,
          fmaf(w4, y4.x, fmaf(w5, y5.x, fmaf(w6, y6.x, w7 * y7.x)))))));
    v.y = fmaf(w0, y0.y, fmaf(w1, y1.y, fmaf(w2, y2.y, fmaf(w3, y3.y,
          fmaf(w4, y4.y, fmaf(w5, y5.y, fmaf(w6, y6.y, w7 * y7.y)))))));
    v.z = fmaf(w0, y0.z, fmaf(w1, y1.z, fmaf(w2, y2.z, fmaf(w3, y3.z,
          fmaf(w4, y4.z, fmaf(w5, y5.z, fmaf(w6, y6.z, w7 * y7.z)))))));
    v.w = fmaf(w0, y0.w, fmaf(w1, y1.w, fmaf(w2, y2.w, fmaf(w3, y3.w,
          fmaf(w4, y4.w, fmaf(w5, y5.w, fmaf(w6, y6.w, w7 * y7.w)))))));

    sP[warp][lane] = v;
    __syncthreads();

    if (warp == 0) {
        float4 acc = sP[0][lane];
#pragma unroll
        for (int j = 1; j < 8; j++) {
            float4 t = sP[j][lane];
            acc.x += t.x; acc.y += t.y; acc.z += t.z; acc.w += t.w;
        }
        float bv0 = __ldg(bv);
        ((float4*)g_V)[g] = make_float4(acc.x + bv0, acc.y + bv0,
                                        acc.z + bv0, acc.w + bv0);
    }
}

// ---------------------------------------------------------------------------
// Kernel 1b: x -> q, k projection (8MB stream). 4-thread split + butterfly
// reduce. (Verbatim from the passing R11-R14 kernels.)
// ---------------------------------------------------------------------------
__global__ void __launch_bounds__(256) projx_kernel(
    const float* __restrict__ x,
    const float* __restrict__ Wq, const float* __restrict__ bq,
    const float* __restrict__ Wk, const float* __restrict__ bk)
{
    const int tid = blockIdx.x * 256 + threadIdx.x;   // [0, 131072)
    const int g   = tid >> 2;                         // float4 pos-group [0, 32768)
    const int s   = tid & 3;
    const int b   = g >> 14;
    const int p4  = g & (HW4 - 1);

    float4 k0 = make_float4(0.f,0.f,0.f,0.f);
    float4 k1 = make_float4(0.f,0.f,0.f,0.f);
    float4 q0 = make_float4(0.f,0.f,0.f,0.f);
    float4 q1 = make_float4(0.f,0.f,0.f,0.f);

    const float4* xb = (const float4*)x + (size_t)b * CC * HW4 + p4;
#pragma unroll
    for (int i = 0; i < 4; i++) {
        int c = s * 4 + i;
        float4 xv = __ldg(xb + c * HW4);
        float wk0 = __ldg(Wk + c), wk1 = __ldg(Wk + CC + c);
        float wq0 = __ldg(Wq + c), wq1 = __ldg(Wq + CC + c);
        k0.x = fmaf(wk0, xv.x, k0.x); k0.y = fmaf(wk0, xv.y, k0.y);
        k0.z = fmaf(wk0, xv.z, k0.z); k0.w = fmaf(wk0, xv.w, k0.w);
        k1.x = fmaf(wk1, xv.x, k1.x); k1.y = fmaf(wk1, xv.y, k1.y);
        k1.z = fmaf(wk1, xv.z, k1.z); k1.w = fmaf(wk1, xv.w, k1.w);
        q0.x = fmaf(wq0, xv.x, q0.x); q0.y = fmaf(wq0, xv.y, q0.y);
        q0.z = fmaf(wq0, xv.z, q0.z); q0.w = fmaf(wq0, xv.w, q0.w);
        q1.x = fmaf(wq1, xv.x, q1.x); q1.y = fmaf(wq1, xv.y, q1.y);
        q1.z = fmaf(wq1, xv.z, q1.z); q1.w = fmaf(wq1, xv.w, q1.w);
    }

#define RED4(f) \
    f += __shfl_xor_sync(0xffffffffu, f, 1); \
    f += __shfl_xor_sync(0xffffffffu, f, 2);
    RED4(k0.x) RED4(k0.y) RED4(k0.z) RED4(k0.w)
    RED4(k1.x) RED4(k1.y) RED4(k1.z) RED4(k1.w)
    RED4(q0.x) RED4(q0.y) RED4(q0.z) RED4(q0.w)
    RED4(q1.x) RED4(q1.y) RED4(q1.z) RED4(q1.w)
#undef RED4

    if (s == 0) {
        float bk0 = __ldg(bk + 0), bk1 = __ldg(bk + 1);
        float bq0 = __ldg(bq + 0), bq1 = __ldg(bq + 1);

        float4* K01o = (float4*)g_K01 + (size_t)g * 2;
        K01o[0] = make_float4(k0.x + bk0, k1.x + bk1, k0.y + bk0, k1.y + bk1);
        K01o[1] = make_float4(k0.z + bk0, k1.z + bk1, k0.w + bk0, k1.w + bk1);

        float4* Q01o = (float4*)g_Q01 + (size_t)g * 2;
        Q01o[0] = make_float4((q0.x + bq0) * LOG2E, (q1.x + bq1) * LOG2E,
                              (q0.y + bq0) * LOG2E, (q1.y + bq1) * LOG2E);
        Q01o[1] = make_float4((q0.z + bq0) * LOG2E, (q1.z + bq1) * LOG2E,
                              (q0.w + bq0) * LOG2E, (q1.w + bq1) * LOG2E);
    }
}

// ---------------------------------------------------------------------------
// Kernel 2: attention, R12-proven inner loop, R14-proven pair-reduce, and a
// SINGLE normalized float written per position (g_res). No epilogue (the
// R14 regression source under the 32-reg cap), no g_part arrays.
// One CTA per (b, h); 512 threads = 2 g-splits x 256 w.
// ---------------------------------------------------------------------------
__global__ void __launch_bounds__(512, 4) attn_kernel(
    const float* __restrict__ gamma)
{
    __shared__ float2 sK[256];     // row h: k at (h, g), all 256 g
    __shared__ float  sV[256];     // row h: v at (h, g)
    __shared__ float2 sRed[256];   // split-1 partial (s, acc)

    const int tid   = threadIdx.x;
    const int split = tid >> 8;            // g-range: [0,128) or [128,256)
    const int w     = tid & 255;
    const int g0    = split << 7;

    const int blk   = blockIdx.x;          // [0, BB*HH)
    const int b     = blk >> 8;
    const int h     = blk & 255;
    const int plane   = b * HW;
    const int rowbase = plane + h * WW;

    // Stage full row k/v (256 entries) into shared: split 0 loads K, 1 loads V.
    if (split == 0) sK[w] = g_K01[rowbase + w];
    else            sV[w] = g_V [rowbase + w];

    const float2 q = g_Q01[rowbase + w];
    __syncthreads();

    const float2* Kc = g_K01 + plane + g0 * WW + w;   // column walk, coalesced
    const float*  Vc = g_V   + plane + g0 * WW + w;

    // Separate col/row accumulator chains (ILP).
    float s_c = 0.0f, acc_c = 0.0f;
    float s_r = 0.0f, acc_r = 0.0f;

#pragma unroll 4
    for (int j = 0; j < 128; j++) {
        // --- column attention (eH), diagonal included (removed below) ---
        float2 kc = Kc[j * WW];
        float  vc = Vc[j * WW];
        float  e  = fmaf(q.x, kc.x, q.y * kc.y);
        float  pe;
        asm("ex2.approx.f32 %0, %1;" : "=f"(pe) : "f"(e));
        s_c  += pe;
        acc_c = fmaf(pe, vc, acc_c);

        // --- row attention (eW), no mask ---
        float2 kr = sK[g0 + j];
        float  vr = sV[g0 + j];
        float  e2 = fmaf(q.x, kr.x, q.y * kr.y);
        float  pe2;
        asm("ex2.approx.f32 %0, %1;" : "=f"(pe2) : "f"(e2));
        s_r  += pe2;
        acc_r = fmaf(pe2, vr, acc_r);
    }

    float s   = s_c + s_r;
    float acc = acc_c + acc_r;

    // Subtract the masked diagonal term (g == h) if it fell in this split.
    if ((unsigned)(h - g0) < 128u) {
        float2 kd = g_K01[rowbase + w];
        float  vd = g_V [rowbase + w];
        float  ed = fmaf(q.x, kd.x, q.y * kd.y);
        float  pd;
        asm("ex2.approx.f32 %0, %1;" : "=f"(pd) : "f"(ed));
        s   -= pd;
        acc  = fmaf(-pd, vd, acc);
    }

    // Pair-reduce the two splits through shared (R14-proven pattern).
    if (split == 1) sRed[w] = make_float2(s, acc);
    __syncthreads();
    if (split == 0) {
        float2 rr = sRed[w];
        g_res[rowbase + w] = __ldg(gamma) * (acc + rr.y) / (s + rr.x);
    }
}

// ---------------------------------------------------------------------------
// Kernel 3: combine res + residual over 16 channels. 8-way channel split
// (grid 1024 -> ~55 warps/SM): oct = idx>>15 handles channels {2*oct, 2*oct+1}
// for pos-group p = idx & 32767. g_res (0.5MB) is L2-hot; 3 independent
// LDG.128 per thread.
// ---------------------------------------------------------------------------
__global__ void __launch_bounds__(256) combine_kernel(
    const float* __restrict__ x,
    float* __restrict__ out)
{
    int idx = blockIdx.x * 256 + threadIdx.x;   // [0, 262144)
    int oct = idx >> 15;                        // 0..7
    int p   = idx & 32767;                      // pos-group [0, BB*HW4)
    int b   = p >> 14;
    int p4  = p & (HW4 - 1);

    float4 r4 = ((const float4*)g_res)[p];

    const float4* xb = (const float4*)x + (size_t)(b * CC + oct * 2) * HW4 + p4;
    float4*       ob = (float4*)out     + (size_t)(b * CC + oct * 2) * HW4 + p4;

    float4 x0 = __ldg(xb);
    float4 x1 = __ldg(xb + HW4);
    ob[0]   = make_float4(r4.x + x0.x, r4.y + x0.y, r4.z + x0.z, r4.w + x0.w);
    ob[HW4] = make_float4(r4.x + x1.x, r4.y + x1.y, r4.z + x1.z, r4.w + x1.w);
}

// ---------------------------------------------------------------------------
// kernel_launch: inputs per metadata order:
//   0:x (B,C,H,W) 1:y (B,64,H,W) 2:Wq (2,16) 3:bq (2) 4:Wk (2,16) 5:bk (2)
//   6:Wv (1,64)  7:bv (1)        8:gamma (1)
// ---------------------------------------------------------------------------
extern "C" void kernel_launch(void* const* d_in, const int* in_sizes, int n_in,
                              void* d_out, int out_size)
{
    const float* x     = (const float*)d_in[0];
    const float* y     = (const float*)d_in[1];
    const float* Wq    = (const float*)d_in[2];
    const float* bq    = (const float*)d_in[3];
    const float* Wk    = (const float*)d_in[4];
    const float* bk    = (const float*)d_in[5];
    const float* Wv    = (const float*)d_in[6];
    const float* bv    = (const float*)d_in[7];
    const float* gamma = (const float*)d_in[8];
    float* out = (float*)d_out;

    projy_kernel<<<1024, 256>>>(y, Wv, bv);
    projx_kernel<<<512, 256>>>(x, Wq, bq, Wk, bk);
    attn_kernel<<<BB * HH, 512>>>(gamma);
    combine_kernel<<<1024, 256>>>(x, out);
}

// round 16
// speedup vs baseline: 1.3083x; 1.0453x over previous
#include <cuda_runtime.h>
#include <cuda_bf16.h>

// Problem constants (fixed by setup_inputs): B=2, C=16, H=W=256, Cctx=64, Cqk=2, Cv=1
#define BB   2
#define CC   16
#define HH   256
#define WW   256
#define CTX  64
#define HW   (HH * WW)          // 65536
#define HW4  (HW / 4)           // 16384
#define LOG2E 1.4426950408889634f

// Scratch (all L2-resident). Each array written by exactly ONE kernel:
//  g_V  : projy output (v per position), also read by projx for packing.
//  g_KV : projx output, packed (k0, k1, v, 0) per position. attn's inner
//         loop is ONE LDG.128 / LDS.128 per logit.
//  g_Q01: projx output, (q0,q1) pre-scaled by log2(e).
//  g_res: attn output, normalized gamma*acc/s per position.
__device__ float  g_V  [BB * HW];
__device__ float4 g_KV [BB * HW];
__device__ float2 g_Q01[BB * HW];
__device__ float  g_res[BB * HW];

// ---------------------------------------------------------------------------
// Kernel 1a: y -> v projection (32MB stream). Warp-level channel split with
// ALL 8 loads front-batched into named regs (bytes-in-flight fix, R14-proven).
// ---------------------------------------------------------------------------
__global__ void __launch_bounds__(256) projy_kernel(
    const float* __restrict__ y,
    const float* __restrict__ Wv, const float* __restrict__ bv)
{
    __shared__ float4 sP[8][32];

    const int warp  = threadIdx.x >> 5;           // channel split 0..7
    const int lane  = threadIdx.x & 31;
    const int g     = blockIdx.x * 32 + lane;     // float4 pos-group [0, 32768)
    const int b     = g >> 14;
    const int p4    = g & (HW4 - 1);

    const float4* yb = (const float4*)y + (size_t)b * CTX * HW4
                                        + (size_t)(warp * 8) * HW4 + p4;
    float4 y0 = __ldg(yb + 0 * HW4);
    float4 y1 = __ldg(yb + 1 * HW4);
    float4 y2 = __ldg(yb + 2 * HW4);
    float4 y3 = __ldg(yb + 3 * HW4);
    float4 y4 = __ldg(yb + 4 * HW4);
    float4 y5 = __ldg(yb + 5 * HW4);
    float4 y6 = __ldg(yb + 6 * HW4);
    float4 y7 = __ldg(yb + 7 * HW4);
    float w0 = __ldg(Wv + warp * 8 + 0);
    float w1 = __ldg(Wv + warp * 8 + 1);
    float w2 = __ldg(Wv + warp * 8 + 2);
    float w3 = __ldg(Wv + warp * 8 + 3);
    float w4 = __ldg(Wv + warp * 8 + 4);
    float w5 = __ldg(Wv + warp * 8 + 5);
    float w6 = __ldg(Wv + warp * 8 + 6);
    float w7 = __ldg(Wv + warp * 8 + 7);

    float4 v;
    v.x = fmaf(w0, y0.x, fmaf(w1, y1.x, fmaf(w2, y2.x, fmaf(w3, y3.x,
          fmaf(w4, y4.x, fmaf(w5, y5.x, fmaf(w6, y6.x, w7 * y7.x)))))));
    v.y = fmaf(w0, y0.y, fmaf(w1, y1.y, fmaf(w2, y2.y, fmaf(w3, y3.y,
          fmaf(w4, y4.y, fmaf(w5, y5.y, fmaf(w6, y6.y, w7 * y7.y)))))));
    v.z = fmaf(w0, y0.z, fmaf(w1, y1.z, fmaf(w2, y2.z, fmaf(w3, y3.z,
          fmaf(w4, y4.z, fmaf(w5, y5.z, fmaf(w6, y6.z, w7 * y7.z)))))));
    v.w = fmaf(w0, y0.w, fmaf(w1, y1.w, fmaf(w2, y2.w, fmaf(w3, y3.w,
          fmaf(w4, y4.w, fmaf(w5, y5.w, fmaf(w6, y6.w, w7 * y7.w)))))));

    sP[warp][lane] = v;
    __syncthreads();

    if (warp == 0) {
        float4 acc = sP[0][lane];
#pragma unroll
        for (int j = 1; j < 8; j++) {
            float4 t = sP[j][lane];
            acc.x += t.x; acc.y += t.y; acc.z += t.z; acc.w += t.w;
        }
        float bv0 = __ldg(bv);
        ((float4*)g_V)[g] = make_float4(acc.x + bv0, acc.y + bv0,
                                        acc.z + bv0, acc.w + bv0);
    }
}

// ---------------------------------------------------------------------------
// Kernel 1b: x -> q, k projection + KV packing. Runs AFTER projy (in-stream
// order), so lane s==0 also reads the finished v (float4 covering its 4
// positions) and writes packed g_KV = (k0, k1, v, 0) — single writer, whole
// 16B words (the R10 hazard was two kernels partial-writing one word).
// ---------------------------------------------------------------------------
__global__ void __launch_bounds__(256) projx_kernel(
    const float* __restrict__ x,
    const float* __restrict__ Wq, const float* __restrict__ bq,
    const float* __restrict__ Wk, const float* __restrict__ bk)
{
    const int tid = blockIdx.x * 256 + threadIdx.x;   // [0, 131072)
    const int g   = tid >> 2;                         // float4 pos-group [0, 32768)
    const int s   = tid & 3;
    const int b   = g >> 14;
    const int p4  = g & (HW4 - 1);

    float4 k0 = make_float4(0.f,0.f,0.f,0.f);
    float4 k1 = make_float4(0.f,0.f,0.f,0.f);
    float4 q0 = make_float4(0.f,0.f,0.f,0.f);
    float4 q1 = make_float4(0.f,0.f,0.f,0.f);

    const float4* xb = (const float4*)x + (size_t)b * CC * HW4 + p4;
#pragma unroll
    for (int i = 0; i < 4; i++) {
        int c = s * 4 + i;
        float4 xv = __ldg(xb + c * HW4);
        float wk0 = __ldg(Wk + c), wk1 = __ldg(Wk + CC + c);
        float wq0 = __ldg(Wq + c), wq1 = __ldg(Wq + CC + c);
        k0.x = fmaf(wk0, xv.x, k0.x); k0.y = fmaf(wk0, xv.y, k0.y);
        k0.z = fmaf(wk0, xv.z, k0.z); k0.w = fmaf(wk0, xv.w, k0.w);
        k1.x = fmaf(wk1, xv.x, k1.x); k1.y = fmaf(wk1, xv.y, k1.y);
        k1.z = fmaf(wk1, xv.z, k1.z); k1.w = fmaf(wk1, xv.w, k1.w);
        q0.x = fmaf(wq0, xv.x, q0.x); q0.y = fmaf(wq0, xv.y, q0.y);
        q0.z = fmaf(wq0, xv.z, q0.z); q0.w = fmaf(wq0, xv.w, q0.w);
        q1.x = fmaf(wq1, xv.x, q1.x); q1.y = fmaf(wq1, xv.y, q1.y);
        q1.z = fmaf(wq1, xv.z, q1.z); q1.w = fmaf(wq1, xv.w, q1.w);
    }

#define RED4(f) \
    f += __shfl_xor_sync(0xffffffffu, f, 1); \
    f += __shfl_xor_sync(0xffffffffu, f, 2);
    RED4(k0.x) RED4(k0.y) RED4(k0.z) RED4(k0.w)
    RED4(k1.x) RED4(k1.y) RED4(k1.z) RED4(k1.w)
    RED4(q0.x) RED4(q0.y) RED4(q0.z) RED4(q0.w)
    RED4(q1.x) RED4(q1.y) RED4(q1.z) RED4(q1.w)
#undef RED4

    if (s == 0) {
        float bk0 = __ldg(bk + 0), bk1 = __ldg(bk + 1);
        float bq0 = __ldg(bq + 0), bq1 = __ldg(bq + 1);
        float4 vv = __ldg((const float4*)g_V + g);   // projy finished (in-order stream)

        float4* KVo = g_KV + (size_t)g * 4;
        KVo[0] = make_float4(k0.x + bk0, k1.x + bk1, vv.x, 0.f);
        KVo[1] = make_float4(k0.y + bk0, k1.y + bk1, vv.y, 0.f);
        KVo[2] = make_float4(k0.z + bk0, k1.z + bk1, vv.z, 0.f);
        KVo[3] = make_float4(k0.w + bk0, k1.w + bk1, vv.w, 0.f);

        float4* Q01o = (float4*)g_Q01 + (size_t)g * 2;
        Q01o[0] = make_float4((q0.x + bq0) * LOG2E, (q1.x + bq1) * LOG2E,
                              (q0.y + bq0) * LOG2E, (q1.y + bq1) * LOG2E);
        Q01o[1] = make_float4((q0.z + bq0) * LOG2E, (q1.z + bq1) * LOG2E,
                              (q0.w + bq0) * LOG2E, (q1.w + bq1) * LOG2E);
    }
}

// ---------------------------------------------------------------------------
// Kernel 2: attention. R12-proven loop STRUCTURE (interleaved col LDG + row
// LDS + 2x EX2 per iteration, 2 g-splits x 256 w per CTA, pair-reduce), but
// with the packed KV: ONE LDG.128 per column logit, ONE LDS.128 per row
// logit. Writes a single normalized float per position (g_res).
// ---------------------------------------------------------------------------
__global__ void __launch_bounds__(512, 4) attn_kernel(
    const float* __restrict__ gamma)
{
    __shared__ float4 sKV [256];   // row h: (k0,k1,v) at (h, g), all 256 g
    __shared__ float2 sRed[256];   // split-1 partial (s, acc)

    const int tid   = threadIdx.x;
    const int split = tid >> 8;            // g-range: [0,128) or [128,256)
    const int w     = tid & 255;
    const int g0    = split << 7;

    const int blk   = blockIdx.x;          // [0, BB*HH)
    const int b     = blk >> 8;
    const int h     = blk & 255;
    const int plane   = b * HW;
    const int rowbase = plane + h * WW;

    // Stage full row KV (256 float4s) into shared (first 256 threads).
    if (split == 0) sKV[w] = g_KV[rowbase + w];

    const float2 q = g_Q01[rowbase + w];
    __syncthreads();

    const float4* Kc = g_KV + plane + g0 * WW + w;   // column walk, coalesced

    // Separate col/row accumulator chains (ILP).
    float s_c = 0.0f, acc_c = 0.0f;
    float s_r = 0.0f, acc_r = 0.0f;

#pragma unroll 4
    for (int j = 0; j < 128; j++) {
        // --- column attention (eH), diagonal included (removed below) ---
        float4 kc = Kc[j * WW];
        float  e  = fmaf(q.x, kc.x, q.y * kc.y);
        float  pe;
        asm("ex2.approx.f32 %0, %1;" : "=f"(pe) : "f"(e));
        s_c  += pe;
        acc_c = fmaf(pe, kc.z, acc_c);

        // --- row attention (eW), no mask ---
        float4 kr = sKV[g0 + j];
        float  e2 = fmaf(q.x, kr.x, q.y * kr.y);
        float  pe2;
        asm("ex2.approx.f32 %0, %1;" : "=f"(pe2) : "f"(e2));
        s_r  += pe2;
        acc_r = fmaf(pe2, kr.z, acc_r);
    }

    float s   = s_c + s_r;
    float acc = acc_c + acc_r;

    // Subtract the masked diagonal term (g == h) if it fell in this split.
    if ((unsigned)(h - g0) < 128u) {
        float4 kd = g_KV[rowbase + w];
        float  ed = fmaf(q.x, kd.x, q.y * kd.y);
        float  pd;
        asm("ex2.approx.f32 %0, %1;" : "=f"(pd) : "f"(ed));
        s   -= pd;
        acc  = fmaf(-pd, kd.z, acc);
    }

    // Pair-reduce the two splits through shared (proven pattern).
    if (split == 1) sRed[w] = make_float2(s, acc);
    __syncthreads();
    if (split == 0) {
        float2 rr = sRed[w];
        g_res[rowbase + w] = __ldg(gamma) * (acc + rr.y) / (s + rr.x);
    }
}

// ---------------------------------------------------------------------------
// Kernel 3: combine res + residual, QUAD-SPLIT (R12-proven index pattern):
// thread handles pos-group p = idx & 32767 for channels [4*quad, 4*quad+4).
// 5 independent LDG.128 per thread (1 res + 4 x).
// ---------------------------------------------------------------------------
__global__ void __launch_bounds__(256) combine_kernel(
    const float* __restrict__ x,
    float* __restrict__ out)
{
    int idx  = blockIdx.x * 256 + threadIdx.x;   // [0, 131072)
    int quad = idx >> 15;                        // channel quad 0..3
    int p    = idx & 32767;                      // pos-group [0, BB*HW4)
    int b    = p >> 14;
    int p4   = p & (HW4 - 1);

    float4 r4 = __ldg((const float4*)g_res + p);

    const float4* xb = (const float4*)x + (size_t)(b * CC + quad * 4) * HW4 + p4;
    float4*       ob = (float4*)out     + (size_t)(b * CC + quad * 4) * HW4 + p4;

    float4 x0 = __ldg(xb + 0 * HW4);
    float4 x1 = __ldg(xb + 1 * HW4);
    float4 x2 = __ldg(xb + 2 * HW4);
    float4 x3 = __ldg(xb + 3 * HW4);
    ob[0 * HW4] = make_float4(r4.x + x0.x, r4.y + x0.y, r4.z + x0.z, r4.w + x0.w);
    ob[1 * HW4] = make_float4(r4.x + x1.x, r4.y + x1.y, r4.z + x1.z, r4.w + x1.w);
    ob[2 * HW4] = make_float4(r4.x + x2.x, r4.y + x2.y, r4.z + x2.z, r4.w + x2.w);
    ob[3 * HW4] = make_float4(r4.x + x3.x, r4.y + x3.y, r4.z + x3.z, r4.w + x3.w);
}

// ---------------------------------------------------------------------------
// kernel_launch: inputs per metadata order:
//   0:x (B,C,H,W) 1:y (B,64,H,W) 2:Wq (2,16) 3:bq (2) 4:Wk (2,16) 5:bk (2)
//   6:Wv (1,64)  7:bv (1)        8:gamma (1)
// ---------------------------------------------------------------------------
extern "C" void kernel_launch(void* const* d_in, const int* in_sizes, int n_in,
                              void* d_out, int out_size)
{
    const float* x     = (const float*)d_in[0];
    const float* y     = (const float*)d_in[1];
    const float* Wq    = (const float*)d_in[2];
    const float* bq    = (const float*)d_in[3];
    const float* Wk    = (const float*)d_in[4];
    const float* bk    = (const float*)d_in[5];
    const float* Wv    = (const float*)d_in[6];
    const float* bv    = (const float*)d_in[7];
    const float* gamma = (const float*)d_in[8];
    float* out = (float*)d_out;

    projy_kernel<<<1024, 256>>>(y, Wv, bv);             // must precede projx
    projx_kernel<<<512, 256>>>(x, Wq, bq, Wk, bk);      // packs KV from g_V
    attn_kernel<<<BB * HH, 512>>>(gamma);
    combine_kernel<<<512, 256>>>(x, out);
}

// round 17
// speedup vs baseline: 1.4444x; 1.1040x over previous
#include <cuda_runtime.h>
#include <cuda_bf16.h>

// Problem constants (fixed by setup_inputs): B=2, C=16, H=W=256, Cctx=64, Cqk=2, Cv=1
#define BB   2
#define CC   16
#define HH   256
#define WW   256
#define CTX  64
#define HW   (HH * WW)          // 65536
#define HW4  (HW / 4)           // 16384
#define LOG2E 1.4426950408889634f

// Scratch (all L2-resident). Each array written by exactly ONE kernel.
__device__ float  g_V  [BB * HW];
__device__ float4 g_KV [BB * HW];   // (k0, k1, v, 0) per position
__device__ float2 g_Q01[BB * HW];   // (q0,q1) pre-scaled by log2(e)
__device__ float  g_res[BB * HW];   // gamma*acc/s per position

// ---------------------------------------------------------------------------
// Kernel 1a: y -> v projection (32MB stream). Warp-level channel split with
// all 8 loads front-batched into named regs. (Verbatim R15/R16 — proven.)
// ---------------------------------------------------------------------------
__global__ void __launch_bounds__(256) projy_kernel(
    const float* __restrict__ y,
    const float* __restrict__ Wv, const float* __restrict__ bv)
{
    __shared__ float4 sP[8][32];

    const int warp  = threadIdx.x >> 5;           // channel split 0..7
    const int lane  = threadIdx.x & 31;
    const int g     = blockIdx.x * 32 + lane;     // float4 pos-group [0, 32768)
    const int b     = g >> 14;
    const int p4    = g & (HW4 - 1);

    const float4* yb = (const float4*)y + (size_t)b * CTX * HW4
                                        + (size_t)(warp * 8) * HW4 + p4;
    float4 y0 = __ldg(yb + 0 * HW4);
    float4 y1 = __ldg(yb + 1 * HW4);
    float4 y2 = __ldg(yb + 2 * HW4);
    float4 y3 = __ldg(yb + 3 * HW4);
    float4 y4 = __ldg(yb + 4 * HW4);
    float4 y5 = __ldg(yb + 5 * HW4);
    float4 y6 = __ldg(yb + 6 * HW4);
    float4 y7 = __ldg(yb + 7 * HW4);
    float w0 = __ldg(Wv + warp * 8 + 0);
    float w1 = __ldg(Wv + warp * 8 + 1);
    float w2 = __ldg(Wv + warp * 8 + 2);
    float w3 = __ldg(Wv + warp * 8 + 3);
    float w4 = __ldg(Wv + warp * 8 + 4);
    float w5 = __ldg(Wv + warp * 8 + 5);
    float w6 = __ldg(Wv + warp * 8 + 6);
    float w7 = __ldg(Wv + warp * 8 + 7);

    float4 v;
    v.x = fmaf(w0, y0.x, fmaf(w1, y1.x, fmaf(w2, y2.x, fmaf(w3, y3.x,
          fmaf(w4, y4.x, fmaf(w5, y5.x, fmaf(w6, y6.x, w7 * y7.x)))))));
    v.y = fmaf(w0, y0.y, fmaf(w1, y1.y, fmaf(w2, y2.y, fmaf(w3, y3.y,
          fmaf(w4, y4.y, fmaf(w5, y5.y, fmaf(w6, y6.y, w7 * y7.y)))))));
    v.z = fmaf(w0, y0.z, fmaf(w1, y1.z, fmaf(w2, y2.z, fmaf(w3, y3.z,
          fmaf(w4, y4.z, fmaf(w5, y5.z, fmaf(w6, y6.z, w7 * y7.z)))))));
    v.w = fmaf(w0, y0.w, fmaf(w1, y1.w, fmaf(w2, y2.w, fmaf(w3, y3.w,
          fmaf(w4, y4.w, fmaf(w5, y5.w, fmaf(w6, y6.w, w7 * y7.w)))))));

    sP[warp][lane] = v;
    __syncthreads();

    if (warp == 0) {
        float4 acc = sP[0][lane];
#pragma unroll
        for (int j = 1; j < 8; j++) {
            float4 t = sP[j][lane];
            acc.x += t.x; acc.y += t.y; acc.z += t.z; acc.w += t.w;
        }
        float bv0 = __ldg(bv);
        ((float4*)g_V)[g] = make_float4(acc.x + bv0, acc.y + bv0,
                                        acc.z + bv0, acc.w + bv0);
    }
}

// ---------------------------------------------------------------------------
// Kernel 1b: x -> q, k projection + KV packing (reads finished g_V; single
// writer of whole 16B words). (Verbatim R16 — proven.)
// ---------------------------------------------------------------------------
__global__ void __launch_bounds__(256) projx_kernel(
    const float* __restrict__ x,
    const float* __restrict__ Wq, const float* __restrict__ bq,
    const float* __restrict__ Wk, const float* __restrict__ bk)
{
    const int tid = blockIdx.x * 256 + threadIdx.x;   // [0, 131072)
    const int g   = tid >> 2;                         // float4 pos-group [0, 32768)
    const int s   = tid & 3;
    const int b   = g >> 14;
    const int p4  = g & (HW4 - 1);

    float4 k0 = make_float4(0.f,0.f,0.f,0.f);
    float4 k1 = make_float4(0.f,0.f,0.f,0.f);
    float4 q0 = make_float4(0.f,0.f,0.f,0.f);
    float4 q1 = make_float4(0.f,0.f,0.f,0.f);

    const float4* xb = (const float4*)x + (size_t)b * CC * HW4 + p4;
#pragma unroll
    for (int i = 0; i < 4; i++) {
        int c = s * 4 + i;
        float4 xv = __ldg(xb + c * HW4);
        float wk0 = __ldg(Wk + c), wk1 = __ldg(Wk + CC + c);
        float wq0 = __ldg(Wq + c), wq1 = __ldg(Wq + CC + c);
        k0.x = fmaf(wk0, xv.x, k0.x); k0.y = fmaf(wk0, xv.y, k0.y);
        k0.z = fmaf(wk0, xv.z, k0.z); k0.w = fmaf(wk0, xv.w, k0.w);
        k1.x = fmaf(wk1, xv.x, k1.x); k1.y = fmaf(wk1, xv.y, k1.y);
        k1.z = fmaf(wk1, xv.z, k1.z); k1.w = fmaf(wk1, xv.w, k1.w);
        q0.x = fmaf(wq0, xv.x, q0.x); q0.y = fmaf(wq0, xv.y, q0.y);
        q0.z = fmaf(wq0, xv.z, q0.z); q0.w = fmaf(wq0, xv.w, q0.w);
        q1.x = fmaf(wq1, xv.x, q1.x); q1.y = fmaf(wq1, xv.y, q1.y);
        q1.z = fmaf(wq1, xv.z, q1.z); q1.w = fmaf(wq1, xv.w, q1.w);
    }

#define RED4(f) \
    f += __shfl_xor_sync(0xffffffffu, f, 1); \
    f += __shfl_xor_sync(0xffffffffu, f, 2);
    RED4(k0.x) RED4(k0.y) RED4(k0.z) RED4(k0.w)
    RED4(k1.x) RED4(k1.y) RED4(k1.z) RED4(k1.w)
    RED4(q0.x) RED4(q0.y) RED4(q0.z) RED4(q0.w)
    RED4(q1.x) RED4(q1.y) RED4(q1.z) RED4(q1.w)
#undef RED4

    if (s == 0) {
        float bk0 = __ldg(bk + 0), bk1 = __ldg(bk + 1);
        float bq0 = __ldg(bq + 0), bq1 = __ldg(bq + 1);
        float4 vv = __ldg((const float4*)g_V + g);

        float4* KVo = g_KV + (size_t)g * 4;
        KVo[0] = make_float4(k0.x + bk0, k1.x + bk1, vv.x, 0.f);
        KVo[1] = make_float4(k0.y + bk0, k1.y + bk1, vv.y, 0.f);
        KVo[2] = make_float4(k0.z + bk0, k1.z + bk1, vv.z, 0.f);
        KVo[3] = make_float4(k0.w + bk0, k1.w + bk1, vv.w, 0.f);

        float4* Q01o = (float4*)g_Q01 + (size_t)g * 2;
        Q01o[0] = make_float4((q0.x + bq0) * LOG2E, (q1.x + bq1) * LOG2E,
                              (q0.y + bq0) * LOG2E, (q1.y + bq1) * LOG2E);
        Q01o[1] = make_float4((q0.z + bq0) * LOG2E, (q1.z + bq1) * LOG2E,
                              (q0.w + bq0) * LOG2E, (q1.w + bq1) * LOG2E);
    }
}

// ---------------------------------------------------------------------------
// Kernel 2: attention, TWO h-rows per thread sharing each column load.
// CTA = (b, h-pair); 512 threads = 2 g-splits x 256 w. Each thread holds q
// for rows h0 and h1 at its w; ONE column LDG.128 per iteration feeds both
// rows' FMA+EX2 (halves column L1/L2 traffic and amortizes issue slots over
// 4 EX2). Both rows' KV staged in shared for the row walk. Per-row diagonal
// subtraction + in-CTA split pair-reduce (one float4 STS), then g_res writes
// for both rows.
// ---------------------------------------------------------------------------
__global__ void __launch_bounds__(512) attn_kernel(
    const float* __restrict__ gamma)
{
    __shared__ float4 sKV [2][256];   // rows h0, h1: (k0,k1,v) over all g
    __shared__ float4 sRed[256];      // split-1 partials: (sA, accA, sB, accB)

    const int tid   = threadIdx.x;
    const int split = tid >> 8;              // g-range: [0,128) or [128,256)
    const int w     = tid & 255;
    const int g0    = split << 7;

    const int blk  = blockIdx.x;             // [0, BB*HH/2) = 256
    const int b    = blk >> 7;
    const int h0   = (blk & 127) << 1;       // even row of the pair
    const int plane = b * HW;
    const int row0  = plane + h0 * WW;
    const int row1  = row0 + WW;

    // Stage both rows' KV: split 0 stages row h0, split 1 stages row h1.
    sKV[split][w] = g_KV[(split ? row1 : row0) + w];

    const float2 qA = g_Q01[row0 + w];
    const float2 qB = g_Q01[row1 + w];
    __syncthreads();

    const float4* Kc = g_KV + plane + g0 * WW + w;   // column walk, coalesced

    float sA_c = 0.f, aA_c = 0.f, sA_r = 0.f, aA_r = 0.f;
    float sB_c = 0.f, aB_c = 0.f, sB_r = 0.f, aB_r = 0.f;

#pragma unroll 4
    for (int j = 0; j < 128; j++) {
        // --- column attention: one load, both rows ---
        float4 kc = Kc[j * WW];
        float  eA = fmaf(qA.x, kc.x, qA.y * kc.y);
        float  eB = fmaf(qB.x, kc.x, qB.y * kc.y);
        float  pA, pB;
        asm("ex2.approx.f32 %0, %1;" : "=f"(pA) : "f"(eA));
        asm("ex2.approx.f32 %0, %1;" : "=f"(pB) : "f"(eB));
        sA_c += pA;  aA_c = fmaf(pA, kc.z, aA_c);
        sB_c += pB;  aB_c = fmaf(pB, kc.z, aB_c);

        // --- row attention: each row its own staged k/v ---
        float4 krA = sKV[0][g0 + j];
        float4 krB = sKV[1][g0 + j];
        float  eA2 = fmaf(qA.x, krA.x, qA.y * krA.y);
        float  eB2 = fmaf(qB.x, krB.x, qB.y * krB.y);
        float  pA2, pB2;
        asm("ex2.approx.f32 %0, %1;" : "=f"(pA2) : "f"(eA2));
        asm("ex2.approx.f32 %0, %1;" : "=f"(pB2) : "f"(eB2));
        sA_r += pA2;  aA_r = fmaf(pA2, krA.z, aA_r);
        sB_r += pB2;  aB_r = fmaf(pB2, krB.z, aB_r);
    }

    float sA = sA_c + sA_r, aA = aA_c + aA_r;
    float sB = sB_c + sB_r, aB = aB_c + aB_r;

    // Subtract masked diagonal terms (g == h_r) if they fell in this split.
    if ((unsigned)(h0 - g0) < 128u) {
        float4 kd = g_KV[row0 + w];
        float  ed = fmaf(qA.x, kd.x, qA.y * kd.y);
        float  pd;
        asm("ex2.approx.f32 %0, %1;" : "=f"(pd) : "f"(ed));
        sA -= pd;  aA = fmaf(-pd, kd.z, aA);
    }
    if ((unsigned)(h0 + 1 - g0) < 128u) {
        float4 kd = g_KV[row1 + w];
        float  ed = fmaf(qB.x, kd.x, qB.y * kd.y);
        float  pd;
        asm("ex2.approx.f32 %0, %1;" : "=f"(pd) : "f"(ed));
        sB -= pd;  aB = fmaf(-pd, kd.z, aB);
    }

    // Pair-reduce the two splits through shared.
    if (split == 1) sRed[w] = make_float4(sA, aA, sB, aB);
    __syncthreads();
    if (split == 0) {
        float4 rr = sRed[w];
        float  gm = __ldg(gamma);
        g_res[row0 + w] = gm * (aA + rr.y) / (sA + rr.x);
        g_res[row1 + w] = gm * (aB + rr.w) / (sB + rr.z);
    }
}

// ---------------------------------------------------------------------------
// Kernel 3: combine res + residual, OCT-SPLIT (R15-measured best: 6.3us,
// occ 62%): oct = idx>>15 handles channels {2*oct, 2*oct+1}.
// ---------------------------------------------------------------------------
__global__ void __launch_bounds__(256) combine_kernel(
    const float* __restrict__ x,
    float* __restrict__ out)
{
    int idx = blockIdx.x * 256 + threadIdx.x;   // [0, 262144)
    int oct = idx >> 15;                        // 0..7
    int p   = idx & 32767;                      // pos-group [0, BB*HW4)
    int b   = p >> 14;
    int p4  = p & (HW4 - 1);

    float4 r4 = __ldg((const float4*)g_res + p);

    const float4* xb = (const float4*)x + (size_t)(b * CC + oct * 2) * HW4 + p4;
    float4*       ob = (float4*)out     + (size_t)(b * CC + oct * 2) * HW4 + p4;

    float4 x0 = __ldg(xb);
    float4 x1 = __ldg(xb + HW4);
    ob[0]   = make_float4(r4.x + x0.x, r4.y + x0.y, r4.z + x0.z, r4.w + x0.w);
    ob[HW4] = make_float4(r4.x + x1.x, r4.y + x1.y, r4.z + x1.z, r4.w + x1.w);
}

// ---------------------------------------------------------------------------
// kernel_launch: inputs per metadata order:
//   0:x (B,C,H,W) 1:y (B,64,H,W) 2:Wq (2,16) 3:bq (2) 4:Wk (2,16) 5:bk (2)
//   6:Wv (1,64)  7:bv (1)        8:gamma (1)
// ---------------------------------------------------------------------------
extern "C" void kernel_launch(void* const* d_in, const int* in_sizes, int n_in,
                              void* d_out, int out_size)
{
    const float* x     = (const float*)d_in[0];
    const float* y     = (const float*)d_in[1];
    const float* Wq    = (const float*)d_in[2];
    const float* bq    = (const float*)d_in[3];
    const float* Wk    = (const float*)d_in[4];
    const float* bk    = (const float*)d_in[5];
    const float* Wv    = (const float*)d_in[6];
    const float* bv    = (const float*)d_in[7];
    const float* gamma = (const float*)d_in[8];
    float* out = (float*)d_out;

    projy_kernel<<<1024, 256>>>(y, Wv, bv);             // must precede projx
    projx_kernel<<<512, 256>>>(x, Wq, bq, Wk, bk);      // packs KV from g_V
    attn_kernel<<<BB * HH / 2, 512>>>(gamma);
    combine_kernel<<<1024, 256>>>(x, out);
}